// round 7
// baseline (speedup 1.0000x reference)
#include <cuda_runtime.h>

#define BB 2
#define CC 32
#define DD 64
#define HH 128
#define WW 128
#define NBC (BB*CC)
#define SLICE (HH*WW)
#define NCTA 1024            // 64 bc x 8 hblocks(16 rows) x 2 zhalves
#define NWARP 4              // 128 threads per CTA

// Per-CTA partials [sum, sx, sy, sz]; fully rewritten each run.
__device__ float4 g_part[NCTA];
__device__ unsigned int g_count;   // zero at load; last CTA resets to 0

// ---- packed f32x2 helpers ----
__device__ __forceinline__ void unpack2(unsigned long long v, float& lo, float& hi) {
    asm("mov.b64 {%0,%1}, %2;" : "=f"(lo), "=f"(hi) : "l"(v));
}
__device__ __forceinline__ void acc2(unsigned long long& acc, unsigned long long v) {
    asm("add.rn.f32x2 %0, %0, %1;" : "+l"(acc) : "l"(v));
}
// acc += |b - a| elementwise (packed)
__device__ __forceinline__ void absdiff_acc2(unsigned long long& acc,
                                             unsigned long long a,
                                             unsigned long long b,
                                             unsigned long long neg1) {
    unsigned long long d;
    asm("fma.rn.f32x2 %0, %1, %2, %3;" : "=l"(d) : "l"(a), "l"(neg1), "l"(b)); // b - a
    asm("and.b64 %0, %0, 0x7FFFFFFF7FFFFFFF;" : "+l"(d));
    asm("add.rn.f32x2 %0, %0, %1;" : "+l"(acc) : "l"(d));
}
__device__ __forceinline__ float hadd2(unsigned long long v) {
    float a, b; unpack2(v, a, b); return a + b;
}

// x-diffs for one row held as (r.x=x0x1, r.y=x2x3)
__device__ __forceinline__ float xdiff_row(const ulonglong2& r, int lane) {
    float x0, x1, x2, x3;
    unpack2(r.x, x0, x1);
    unpack2(r.y, x2, x3);
    const float nlx = __shfl_down_sync(0xffffffffu, x0, 1);
    float s = fabsf(x1 - x0) + fabsf(x2 - x1) + fabsf(x3 - x2);
    if (lane < 31) s += fabsf(nlx - x3);
    return s;
}

// CTA = (bc, 16-row block, z-half). 4 warps; warp w carries rows h0..h0+3
// (h0 = hb*16 + 4w) across 32 z-slices. 3 of 4 y-diffs are register-register;
// the seam y-diff loads row h0+4 (L1 hit). z-diff uses the prefetched
// next-slice quad. zh=0 additionally loads slice 32 once for the z seam.
__global__ void __launch_bounds__(128) fused_kernel(const float* __restrict__ seg,
                                                    float* __restrict__ out) {
    const int cta  = blockIdx.x;
    const int bc   = cta >> 4;
    const int rem  = cta & 15;
    const int hb   = rem >> 1;           // 0..7 (16-row blocks)
    const int zh   = rem & 1;
    const int warp = threadIdx.x >> 5;
    const int lane = threadIdx.x & 31;
    const int h0   = hb * 16 + warp * 4;
    const bool has_y = (h0 + 4 < HH);    // false only for rows 124..127
    const unsigned long long neg1 = 0xBF800000BF800000ULL;

    const float* p = seg + (size_t)bc * DD * SLICE + (size_t)(zh * 32) * SLICE + h0 * WW;

    unsigned long long acc_s = 0ULL, acc_y = 0ULL, acc_z = 0ULL;
    float sx = 0.f;

    ulonglong2 c[4];
    #pragma unroll
    for (int r = 0; r < 4; r++)
        c[r] = reinterpret_cast<const ulonglong2*>(p + r * WW)[lane];

    #pragma unroll 1
    for (int i = 0; i < 31; i++) {
        // prefetch next-slice quad + y-seam row (5 independent loads)
        ulonglong2 n[4];
        #pragma unroll
        for (int r = 0; r < 4; r++)
            n[r] = reinterpret_cast<const ulonglong2*>(p + SLICE + r * WW)[lane];
        ulonglong2 yn;
        if (has_y) yn = reinterpret_cast<const ulonglong2*>(p + 4 * WW)[lane];

        // slice sums + x-diffs
        #pragma unroll
        for (int r = 0; r < 4; r++) {
            acc2(acc_s, c[r].x); acc2(acc_s, c[r].y);
            sx += xdiff_row(c[r], lane);
        }
        // y: 3 in-quad diffs + seam
        #pragma unroll
        for (int r = 0; r < 3; r++) {
            absdiff_acc2(acc_y, c[r].x, c[r + 1].x, neg1);
            absdiff_acc2(acc_y, c[r].y, c[r + 1].y, neg1);
        }
        if (has_y) {
            absdiff_acc2(acc_y, c[3].x, yn.x, neg1);
            absdiff_acc2(acc_y, c[3].y, yn.y, neg1);
        }
        // z: diff vs prefetched next slice
        #pragma unroll
        for (int r = 0; r < 4; r++) {
            absdiff_acc2(acc_z, c[r].x, n[r].x, neg1);
            absdiff_acc2(acc_z, c[r].y, n[r].y, neg1);
            c[r] = n[r];
        }
        p += SLICE;
    }

    // epilogue: local slice 31 (global d = zh*32 + 31)
    {
        ulonglong2 yn;
        if (has_y) yn = reinterpret_cast<const ulonglong2*>(p + 4 * WW)[lane];

        #pragma unroll
        for (int r = 0; r < 4; r++) {
            acc2(acc_s, c[r].x); acc2(acc_s, c[r].y);
            sx += xdiff_row(c[r], lane);
        }
        #pragma unroll
        for (int r = 0; r < 3; r++) {
            absdiff_acc2(acc_y, c[r].x, c[r + 1].x, neg1);
            absdiff_acc2(acc_y, c[r].y, c[r + 1].y, neg1);
        }
        if (has_y) {
            absdiff_acc2(acc_y, c[3].x, yn.x, neg1);
            absdiff_acc2(acc_y, c[3].y, yn.y, neg1);
        }
        if (zh == 0) {   // z seam (slice 31 vs 32) owned by left CTA
            #pragma unroll
            for (int r = 0; r < 4; r++) {
                const ulonglong2 n = reinterpret_cast<const ulonglong2*>(p + SLICE + r * WW)[lane];
                absdiff_acc2(acc_z, c[r].x, n.x, neg1);
                absdiff_acc2(acc_z, c[r].y, n.y, neg1);
            }
        }
    }

    float ssum = hadd2(acc_s);
    float sy   = hadd2(acc_y);
    float sz   = hadd2(acc_z);

    #pragma unroll
    for (int off = 16; off > 0; off >>= 1) {
        ssum += __shfl_xor_sync(0xffffffffu, ssum, off);
        sx   += __shfl_xor_sync(0xffffffffu, sx,   off);
        sy   += __shfl_xor_sync(0xffffffffu, sy,   off);
        sz   += __shfl_xor_sync(0xffffffffu, sz,   off);
    }

    __shared__ float sh[4][NWARP];
    if (lane == 0) { sh[0][warp] = ssum; sh[1][warp] = sx; sh[2][warp] = sy; sh[3][warp] = sz; }
    __syncthreads();

    __shared__ bool s_last;
    if (threadIdx.x == 0) {
        float t0 = 0.f, t1 = 0.f, t2 = 0.f, t3 = 0.f;
        #pragma unroll
        for (int w = 0; w < NWARP; w++) {
            t0 += sh[0][w]; t1 += sh[1][w]; t2 += sh[2][w]; t3 += sh[3][w];
        }
        g_part[cta] = make_float4(t0, t1, t2, t3);
        __threadfence();
        const unsigned old = atomicAdd(&g_count, 1u);
        s_last = (old == NCTA - 1);
    }
    __syncthreads();
    if (!s_last) return;

    // ---- finalize in the last CTA (128 threads) ----
    __threadfence();

    const int tid = threadIdx.x;
    double loss = 0.0, tx = 0.0, ty = 0.0, tz = 0.0;
    if (tid < NBC) {
        double crn = 0.0, rt = 0.0;
        #pragma unroll
        for (int k = 0; k < 16; k++) {          // 8 hblocks x 2 zhalves
            const float4 a = g_part[tid * 16 + k];
            if ((k & 1) == 0) crn += (double)a.x;   // zh=0 -> crown (d 0..31)
            else              rt  += (double)a.x;   // zh=1 -> root  (d 32..63)
            tx += (double)a.y; ty += (double)a.z; tz += (double)a.w;
        }
        if ((crn + rt) > 0.0 && rt > 0.0) {
            const double r = crn / rt - 1.2;
            loss = r * r;
        }
    }

    #pragma unroll
    for (int off = 16; off > 0; off >>= 1) {
        loss += __shfl_xor_sync(0xffffffffu, loss, off);
        tx   += __shfl_xor_sync(0xffffffffu, tx,   off);
        ty   += __shfl_xor_sync(0xffffffffu, ty,   off);
        tz   += __shfl_xor_sync(0xffffffffu, tz,   off);
    }

    __shared__ double shd[4][NWARP];
    if (lane == 0) { shd[0][warp] = loss; shd[1][warp] = tx; shd[2][warp] = ty; shd[3][warp] = tz; }
    __syncthreads();

    if (tid == 0) {
        double L = 0.0, Tx = 0.0, Ty = 0.0, Tz = 0.0;
        #pragma unroll
        for (int w = 0; w < NWARP; w++) {
            L += shd[0][w]; Tx += shd[1][w]; Ty += shd[2][w]; Tz += shd[3][w];
        }
        const double cr_loss = L / (double)NBC;
        const double Nx = (double)BB * CC * DD * HH * (WW - 1);
        const double Ny = (double)BB * CC * DD * (HH - 1) * WW;
        const double Nz = (double)BB * CC * (DD - 1) * HH * WW;
        const double tv = Tx / Nx + Ty / Ny + Tz / Nz;

        const double crown_root = cr_loss * 2.0;   // CROWN_ROOT_W
        const double smooth     = tv * 1.5;        // SMOOTH_W
        out[0] = (float)crown_root;
        out[1] = (float)smooth;
        out[2] = (float)(crown_root + smooth);

        g_count = 0;   // reset for next graph replay
    }
}

extern "C" void kernel_launch(void* const* d_in, const int* in_sizes, int n_in,
                              void* d_out, int out_size) {
    const float* seg = (const float*)d_in[0];
    float* out = (float*)d_out;
    fused_kernel<<<NCTA, 128>>>(seg, out);
}

// round 8
// speedup vs baseline: 1.0384x; 1.0384x over previous
#include <cuda_runtime.h>
#include <cstdint>

#define BB 2
#define CC 32
#define DD 64
#define HH 128
#define WW 128
#define NBC (BB*CC)
#define SLICE (HH*WW)
#define NCTA 1024            // 64 bc x 8 hblocks(16 rows) x 2 zhalves
#define NWARP 4
#define NSTG 3               // pipeline stages
#define ROWB 512             // bytes per row (128 floats)
#define STG_BYTES (17*ROWB)  // 17 rows: 16 own + 1 y-seam

// Per-CTA partials [sum, sx, sy, sz]; fully rewritten each run.
__device__ float4 g_part[NCTA];
__device__ unsigned int g_count;   // zero at load; last CTA resets to 0

// ---- packed f32x2 helpers ----
__device__ __forceinline__ void unpack2(unsigned long long v, float& lo, float& hi) {
    asm("mov.b64 {%0,%1}, %2;" : "=f"(lo), "=f"(hi) : "l"(v));
}
__device__ __forceinline__ void acc2(unsigned long long& acc, unsigned long long v) {
    asm("add.rn.f32x2 %0, %0, %1;" : "+l"(acc) : "l"(v));
}
__device__ __forceinline__ void absdiff_acc2(unsigned long long& acc,
                                             unsigned long long a,
                                             unsigned long long b,
                                             unsigned long long neg1) {
    unsigned long long d;
    asm("fma.rn.f32x2 %0, %1, %2, %3;" : "=l"(d) : "l"(a), "l"(neg1), "l"(b)); // b - a
    asm("and.b64 %0, %0, 0x7FFFFFFF7FFFFFFF;" : "+l"(d));
    asm("add.rn.f32x2 %0, %0, %1;" : "+l"(acc) : "l"(d));
}
__device__ __forceinline__ float hadd2(unsigned long long v) {
    float a, b; unpack2(v, a, b); return a + b;
}

__device__ __forceinline__ ulonglong2 lds128(uint32_t a) {
    ulonglong2 v;
    asm volatile("ld.shared.v2.u64 {%0, %1}, [%2];" : "=l"(v.x), "=l"(v.y) : "r"(a));
    return v;
}

__device__ __forceinline__ void waitbar(uint32_t mbar, uint32_t parity) {
    asm volatile(
        "{\n\t"
        ".reg .pred P1;\n\t"
        "WAIT_LOOP_%=:\n\t"
        "mbarrier.try_wait.parity.acquire.cta.shared::cta.b64 P1, [%0], %1, 0x989680;\n\t"
        "@P1 bra.uni WAIT_DONE_%=;\n\t"
        "bra.uni WAIT_LOOP_%=;\n\t"
        "WAIT_DONE_%=:\n\t"
        "}"
        :: "r"(mbar), "r"(parity) : "memory");
}

__device__ __forceinline__ void bulk_load(uint32_t dst_smem, const void* src,
                                          uint32_t nbytes, uint32_t mbar) {
    asm volatile("mbarrier.arrive.expect_tx.shared.b64 _, [%0], %1;"
                 :: "r"(mbar), "r"(nbytes) : "memory");
    asm volatile(
        "cp.async.bulk.shared::cluster.global.mbarrier::complete_tx::bytes "
        "[%0], [%1], %2, [%3];"
        :: "r"(dst_smem), "l"(src), "r"(nbytes), "r"(mbar) : "memory");
}

// x-diffs for one row held as (r.x=x0x1, r.y=x2x3)
__device__ __forceinline__ float xdiff_row(const ulonglong2& r, int lane) {
    float x0, x1, x2, x3;
    unpack2(r.x, x0, x1);
    unpack2(r.y, x2, x3);
    const float nlx = __shfl_down_sync(0xffffffffu, x0, 1);
    float s = fabsf(x1 - x0) + fabsf(x2 - x1) + fabsf(x3 - x2);
    if (lane < 31) s += fabsf(nlx - x3);
    return s;
}

// CTA = (bc, 16-row block, z-half). Thread 0 streams 17-row slices via
// cp.async.bulk into a 3-stage smem ring; 4 warps consume. Warp w handles
// buffer rows 4w..4w+3; y-diffs use buffer rows (incl. row 16 = seam);
// z-diffs read the next stage. zh=0 loads one extra slice for the z-seam.
__global__ void __launch_bounds__(128) fused_kernel(const float* __restrict__ seg,
                                                    float* __restrict__ out) {
    __shared__ __align__(128) char buf[NSTG][STG_BYTES];
    __shared__ __align__(8) unsigned long long mbar[NSTG];
    __shared__ float shf[4][NWARP];
    __shared__ double shd[4][NWARP];
    __shared__ bool s_last;

    const int cta  = blockIdx.x;
    const int bc   = cta >> 4;
    const int rem  = cta & 15;
    const int hb   = rem >> 1;           // 0..7
    const int zh   = rem & 1;
    const int tid  = threadIdx.x;
    const int warp = tid >> 5;
    const int lane = tid & 31;
    const bool has_y = (hb < 7);                 // row 16 (seam) exists
    const uint32_t nbytes = (has_y ? 17u : 16u) * ROWB;
    const int nload = 32 + (zh == 0 ? 1 : 0);
    const unsigned long long neg1 = 0xBF800000BF800000ULL;

    const float* src0 = seg + ((size_t)bc * DD + (size_t)zh * 32) * SLICE + (hb * 16) * WW;

    const uint32_t buf0 = (uint32_t)__cvta_generic_to_shared(&buf[0][0]);
    const uint32_t mb0  = (uint32_t)__cvta_generic_to_shared(&mbar[0]);

    if (tid == 0) {
        #pragma unroll
        for (int s = 0; s < NSTG; s++)
            asm volatile("mbarrier.init.shared.b64 [%0], 1;" :: "r"(mb0 + 8*s) : "memory");
        asm volatile("fence.proxy.async.shared::cta;" ::: "memory");
        #pragma unroll
        for (int i = 0; i < NSTG; i++)   // nload >= 32 > NSTG always
            bulk_load(buf0 + i * STG_BYTES, src0 + (size_t)i * SLICE, nbytes, mb0 + 8*i);
    }
    __syncthreads();

    unsigned long long acc_s = 0ULL, acc_y = 0ULL, acc_z = 0ULL;
    float sx = 0.f;
    const uint32_t abase = buf0 + (uint32_t)(warp * 4 * ROWB + lane * 16);
    const bool warp_has_row4 = (warp < 3) || has_y;

    waitbar(mb0, 0);   // stage 0, round 0

    #pragma unroll 1
    for (int d = 0; d < 32; d++) {
        const int cs = d % NSTG;
        const int ns = (d + 1) % NSTG;
        const bool needs_next = (d < 31) || (zh == 0);
        if (needs_next)
            waitbar(mb0 + 8*ns, ((uint32_t)(d + 1) / NSTG) & 1u);

        const uint32_t ca = abase + cs * STG_BYTES;
        const ulonglong2 c0 = lds128(ca);
        const ulonglong2 c1 = lds128(ca + ROWB);
        const ulonglong2 c2 = lds128(ca + 2*ROWB);
        const ulonglong2 c3 = lds128(ca + 3*ROWB);

        acc2(acc_s, c0.x); acc2(acc_s, c0.y);
        acc2(acc_s, c1.x); acc2(acc_s, c1.y);
        acc2(acc_s, c2.x); acc2(acc_s, c2.y);
        acc2(acc_s, c3.x); acc2(acc_s, c3.y);

        sx += xdiff_row(c0, lane);
        sx += xdiff_row(c1, lane);
        sx += xdiff_row(c2, lane);
        sx += xdiff_row(c3, lane);

        // y: 3 in-quad + seam (row 4w+4, in-buffer)
        absdiff_acc2(acc_y, c0.x, c1.x, neg1); absdiff_acc2(acc_y, c0.y, c1.y, neg1);
        absdiff_acc2(acc_y, c1.x, c2.x, neg1); absdiff_acc2(acc_y, c1.y, c2.y, neg1);
        absdiff_acc2(acc_y, c2.x, c3.x, neg1); absdiff_acc2(acc_y, c2.y, c3.y, neg1);
        if (warp_has_row4) {
            const ulonglong2 yn = lds128(ca + 4*ROWB);
            absdiff_acc2(acc_y, c3.x, yn.x, neg1); absdiff_acc2(acc_y, c3.y, yn.y, neg1);
        }

        // z: vs next stage (same rows)
        if (needs_next) {
            const uint32_t na = abase + ns * STG_BYTES;
            const ulonglong2 n0 = lds128(na);
            const ulonglong2 n1 = lds128(na + ROWB);
            const ulonglong2 n2 = lds128(na + 2*ROWB);
            const ulonglong2 n3 = lds128(na + 3*ROWB);
            absdiff_acc2(acc_z, c0.x, n0.x, neg1); absdiff_acc2(acc_z, c0.y, n0.y, neg1);
            absdiff_acc2(acc_z, c1.x, n1.x, neg1); absdiff_acc2(acc_z, c1.y, n1.y, neg1);
            absdiff_acc2(acc_z, c2.x, n2.x, neg1); absdiff_acc2(acc_z, c2.y, n2.y, neg1);
            absdiff_acc2(acc_z, c3.x, n3.x, neg1); absdiff_acc2(acc_z, c3.y, n3.y, neg1);
        }

        __syncthreads();   // all reads of stage cs done -> safe to refill
        if (tid == 0 && d + NSTG < nload)
            bulk_load(buf0 + cs * STG_BYTES, src0 + (size_t)(d + NSTG) * SLICE,
                      nbytes, mb0 + 8*cs);
    }

    float ssum = hadd2(acc_s);
    float sy   = hadd2(acc_y);
    float sz   = hadd2(acc_z);

    #pragma unroll
    for (int off = 16; off > 0; off >>= 1) {
        ssum += __shfl_xor_sync(0xffffffffu, ssum, off);
        sx   += __shfl_xor_sync(0xffffffffu, sx,   off);
        sy   += __shfl_xor_sync(0xffffffffu, sy,   off);
        sz   += __shfl_xor_sync(0xffffffffu, sz,   off);
    }

    if (lane == 0) { shf[0][warp] = ssum; shf[1][warp] = sx; shf[2][warp] = sy; shf[3][warp] = sz; }
    __syncthreads();

    if (tid == 0) {
        float t0 = 0.f, t1 = 0.f, t2 = 0.f, t3 = 0.f;
        #pragma unroll
        for (int w = 0; w < NWARP; w++) {
            t0 += shf[0][w]; t1 += shf[1][w]; t2 += shf[2][w]; t3 += shf[3][w];
        }
        g_part[cta] = make_float4(t0, t1, t2, t3);
        __threadfence();
        const unsigned old = atomicAdd(&g_count, 1u);
        s_last = (old == NCTA - 1);
    }
    __syncthreads();
    if (!s_last) return;

    // ---- finalize in the last CTA (128 threads) ----
    __threadfence();

    double loss = 0.0, tx = 0.0, ty = 0.0, tz = 0.0;
    if (tid < NBC) {
        double crn = 0.0, rt = 0.0;
        #pragma unroll
        for (int k = 0; k < 16; k++) {          // 8 hblocks x 2 zhalves
            const float4 a = g_part[tid * 16 + k];
            if ((k & 1) == 0) crn += (double)a.x;   // zh=0 -> crown (d 0..31)
            else              rt  += (double)a.x;   // zh=1 -> root  (d 32..63)
            tx += (double)a.y; ty += (double)a.z; tz += (double)a.w;
        }
        if ((crn + rt) > 0.0 && rt > 0.0) {
            const double r = crn / rt - 1.2;
            loss = r * r;
        }
    }

    #pragma unroll
    for (int off = 16; off > 0; off >>= 1) {
        loss += __shfl_xor_sync(0xffffffffu, loss, off);
        tx   += __shfl_xor_sync(0xffffffffu, tx,   off);
        ty   += __shfl_xor_sync(0xffffffffu, ty,   off);
        tz   += __shfl_xor_sync(0xffffffffu, tz,   off);
    }

    if (lane == 0) { shd[0][warp] = loss; shd[1][warp] = tx; shd[2][warp] = ty; shd[3][warp] = tz; }
    __syncthreads();

    if (tid == 0) {
        double L = 0.0, Tx = 0.0, Ty = 0.0, Tz = 0.0;
        #pragma unroll
        for (int w = 0; w < NWARP; w++) {
            L += shd[0][w]; Tx += shd[1][w]; Ty += shd[2][w]; Tz += shd[3][w];
        }
        const double cr_loss = L / (double)NBC;
        const double Nx = (double)BB * CC * DD * HH * (WW - 1);
        const double Ny = (double)BB * CC * DD * (HH - 1) * WW;
        const double Nz = (double)BB * CC * (DD - 1) * HH * WW;
        const double tv = Tx / Nx + Ty / Ny + Tz / Nz;

        const double crown_root = cr_loss * 2.0;   // CROWN_ROOT_W
        const double smooth     = tv * 1.5;        // SMOOTH_W
        out[0] = (float)crown_root;
        out[1] = (float)smooth;
        out[2] = (float)(crown_root + smooth);

        g_count = 0;   // reset for next graph replay
    }
}

extern "C" void kernel_launch(void* const* d_in, const int* in_sizes, int n_in,
                              void* d_out, int out_size) {
    const float* seg = (const float*)d_in[0];
    float* out = (float*)d_out;
    fused_kernel<<<NCTA, 128>>>(seg, out);
}